// round 3
// baseline (speedup 1.0000x reference)
#include <cuda_runtime.h>

#define B_   8
#define N_   4096
#define E_   2048
#define C_   128
#define EPS_ 1e-6f

#define KC   16
#define SPAD 4
#define SROW (C_ + SPAD)

// ---------------- static device scratch (no allocs allowed) ----------------
__device__ float g_dv[B_ * N_];              // Dv^{-1/2}
__device__ float g_de_part[B_ * 8 * E_];     // partial hyperedge-degree sums
__device__ float g_de_inv[B_ * E_];          // De^{-1}
__device__ float g_M[(size_t)B_ * E_ * C_];  // intermediate H^T (x Dv^-1/2) De^-1
__device__ float g_out2[(size_t)B_ * N_ * C_];
__device__ float g_Wt[C_ * C_];              // W^T (k-major)

// ---------------- Dv^{-1/2}: one block per (b,n) row ----------------
__global__ void dv_kernel(const float* __restrict__ H) {
    int row = blockIdx.x;  // b*N + n
    const float4* p = (const float4*)(H + (size_t)row * E_);
    float s = 0.f;
#pragma unroll
    for (int i = 0; i < 4; i++) {
        float4 v = p[threadIdx.x + i * 128];
        s += v.x + v.y + v.z + v.w;
    }
    __shared__ float red[4];
#pragma unroll
    for (int o = 16; o > 0; o >>= 1) s += __shfl_down_sync(0xffffffffu, s, o);
    if ((threadIdx.x & 31) == 0) red[threadIdx.x >> 5] = s;
    __syncthreads();
    if (threadIdx.x == 0) {
        float t = red[0] + red[1] + red[2] + red[3];
        g_dv[row] = rsqrtf(t + EPS_);
    }
}

// ---------------- De partial sums: column sums over 512-row chunks ----------------
__global__ void de_part_kernel(const float* __restrict__ H) {
    int e = blockIdx.x * 256 + threadIdx.x;  // gridDim.x = E/256
    int chunk = blockIdx.y;                  // 8 chunks of 512 rows
    int b = blockIdx.z;
    const float* p = H + ((size_t)b * N_ + (size_t)chunk * 512) * E_ + e;
    float s0 = 0.f, s1 = 0.f, s2 = 0.f, s3 = 0.f;
#pragma unroll 4
    for (int n = 0; n < 512; n += 4) {
        s0 += p[(size_t)(n + 0) * E_];
        s1 += p[(size_t)(n + 1) * E_];
        s2 += p[(size_t)(n + 2) * E_];
        s3 += p[(size_t)(n + 3) * E_];
    }
    g_de_part[((b * 8) + chunk) * E_ + e] = (s0 + s1) + (s2 + s3);
}

__global__ void de_final_kernel() {
    int idx = blockIdx.x * 256 + threadIdx.x;  // b*E + e
    int b = idx >> 11, e = idx & (E_ - 1);
    float s = 0.f;
#pragma unroll
    for (int c = 0; c < 8; c++) s += g_de_part[(b * 8 + c) * E_ + e];
    g_de_inv[idx] = 1.0f / (s + EPS_);
}

// ---------------- W transpose (once, tiny) ----------------
__global__ void wt_kernel(const float* __restrict__ W) {
    int i = blockIdx.x * 256 + threadIdx.x;  // c*128 + k
    int c = i >> 7, k = i & 127;
    g_Wt[k * C_ + c] = W[i];
}

// ============ GEMM1: M[b,e,c] = sum_n H[b,n,e] * x[b,n,c]*dv[b,n]; *De^-1 ============
__global__ __launch_bounds__(256) void gemm1_kernel(const float* __restrict__ H,
                                                    const float* __restrict__ x) {
    __shared__ float As[2][KC][SROW];
    __shared__ float Bs[2][KC][SROW];
    const int b = blockIdx.y;
    const int e0 = blockIdx.x * 128;
    const int tid = threadIdx.x;
    const int tx = tid & 15, ty = tid >> 4;

    const float* Hb = H + (size_t)b * N_ * E_;
    const float* xb = x + (size_t)b * N_ * C_;
    const float* dvb = g_dv + b * N_;

    float acc[8][8];
#pragma unroll
    for (int i = 0; i < 8; i++)
#pragma unroll
        for (int j = 0; j < 8; j++) acc[i][j] = 0.f;

    float4 ra[2], rb[2];
    // prologue: tile 0
#pragma unroll
    for (int i = 0; i < 2; i++) {
        int idx = tid + i * 256, kk = idx >> 5, q = idx & 31;
        ra[i] = *(const float4*)(Hb + (size_t)kk * E_ + e0 + q * 4);
        float4 v = *(const float4*)(xb + (size_t)kk * C_ + q * 4);
        float s = dvb[kk];
        v.x *= s; v.y *= s; v.z *= s; v.w *= s;
        rb[i] = v;
    }
#pragma unroll
    for (int i = 0; i < 2; i++) {
        int idx = tid + i * 256, kk = idx >> 5, q = idx & 31;
        *(float4*)&As[0][kk][q * 4] = ra[i];
        *(float4*)&Bs[0][kk][q * 4] = rb[i];
    }
    __syncthreads();

    const int NK = N_ / KC;  // 256
    for (int kt = 0; kt < NK; kt++) {
        int cur = kt & 1;
        if (kt + 1 < NK) {
            int n0 = (kt + 1) * KC;
#pragma unroll
            for (int i = 0; i < 2; i++) {
                int idx = tid + i * 256, kk = idx >> 5, q = idx & 31;
                ra[i] = *(const float4*)(Hb + (size_t)(n0 + kk) * E_ + e0 + q * 4);
                float4 v = *(const float4*)(xb + (size_t)(n0 + kk) * C_ + q * 4);
                float s = dvb[n0 + kk];
                v.x *= s; v.y *= s; v.z *= s; v.w *= s;
                rb[i] = v;
            }
        }
#pragma unroll
        for (int kk = 0; kk < KC; kk++) {
            float4 a0 = *(const float4*)&As[cur][kk][ty * 8];
            float4 a1 = *(const float4*)&As[cur][kk][ty * 8 + 4];
            float4 b0 = *(const float4*)&Bs[cur][kk][tx * 8];
            float4 b1 = *(const float4*)&Bs[cur][kk][tx * 8 + 4];
            float a[8] = {a0.x, a0.y, a0.z, a0.w, a1.x, a1.y, a1.z, a1.w};
            float bb[8] = {b0.x, b0.y, b0.z, b0.w, b1.x, b1.y, b1.z, b1.w};
#pragma unroll
            for (int i = 0; i < 8; i++)
#pragma unroll
                for (int j = 0; j < 8; j++) acc[i][j] += a[i] * bb[j];
        }
        if (kt + 1 < NK) {
            int nb = cur ^ 1;
#pragma unroll
            for (int i = 0; i < 2; i++) {
                int idx = tid + i * 256, kk = idx >> 5, q = idx & 31;
                *(float4*)&As[nb][kk][q * 4] = ra[i];
                *(float4*)&Bs[nb][kk][q * 4] = rb[i];
            }
        }
        __syncthreads();
    }

    float* Mb = g_M + (size_t)b * E_ * C_;
    const float* deb = g_de_inv + b * E_;
#pragma unroll
    for (int i = 0; i < 8; i++) {
        int e = e0 + ty * 8 + i;
        float s = deb[e];
        float* op = Mb + (size_t)e * C_ + tx * 8;
        *(float4*)op = make_float4(acc[i][0] * s, acc[i][1] * s, acc[i][2] * s, acc[i][3] * s);
        *(float4*)(op + 4) = make_float4(acc[i][4] * s, acc[i][5] * s, acc[i][6] * s, acc[i][7] * s);
    }
}

// ============ GEMM2: out2[b,n,c] = (sum_e H[b,n,e] * M[b,e,c]) * dv[b,n] ============
__global__ __launch_bounds__(256) void gemm2_kernel(const float* __restrict__ H) {
    __shared__ float As[2][KC][SROW];
    __shared__ float Bs[2][KC][SROW];
    const int b = blockIdx.y;
    const int n0 = blockIdx.x * 128;
    const int tid = threadIdx.x;
    const int tx = tid & 15, ty = tid >> 4;

    const float* Hb = H + ((size_t)b * N_ + n0) * E_;
    const float* Mb = g_M + (size_t)b * E_ * C_;

    float acc[8][8];
#pragma unroll
    for (int i = 0; i < 8; i++)
#pragma unroll
        for (int j = 0; j < 8; j++) acc[i][j] = 0.f;

    float4 ra[2], rb[2];
#pragma unroll
    for (int i = 0; i < 2; i++) {
        int idx = tid + i * 256;
        int row = idx >> 2, q = idx & 3;
        ra[i] = *(const float4*)(Hb + (size_t)row * E_ + q * 4);
        int kk = idx >> 5, qc = idx & 31;
        rb[i] = *(const float4*)(Mb + (size_t)kk * C_ + qc * 4);
    }
#pragma unroll
    for (int i = 0; i < 2; i++) {
        int idx = tid + i * 256;
        int row = idx >> 2, q = idx & 3;
        As[0][q * 4 + 0][row] = ra[i].x;
        As[0][q * 4 + 1][row] = ra[i].y;
        As[0][q * 4 + 2][row] = ra[i].z;
        As[0][q * 4 + 3][row] = ra[i].w;
        int kk = idx >> 5, qc = idx & 31;
        *(float4*)&Bs[0][kk][qc * 4] = rb[i];
    }
    __syncthreads();

    const int NK = E_ / KC;  // 128
    for (int kt = 0; kt < NK; kt++) {
        int cur = kt & 1;
        if (kt + 1 < NK) {
            int k0 = (kt + 1) * KC;
#pragma unroll
            for (int i = 0; i < 2; i++) {
                int idx = tid + i * 256;
                int row = idx >> 2, q = idx & 3;
                ra[i] = *(const float4*)(Hb + (size_t)row * E_ + k0 + q * 4);
                int kk = idx >> 5, qc = idx & 31;
                rb[i] = *(const float4*)(Mb + (size_t)(k0 + kk) * C_ + qc * 4);
            }
        }
#pragma unroll
        for (int kk = 0; kk < KC; kk++) {
            float4 a0 = *(const float4*)&As[cur][kk][ty * 8];
            float4 a1 = *(const float4*)&As[cur][kk][ty * 8 + 4];
            float4 b0 = *(const float4*)&Bs[cur][kk][tx * 8];
            float4 b1 = *(const float4*)&Bs[cur][kk][tx * 8 + 4];
            float a[8] = {a0.x, a0.y, a0.z, a0.w, a1.x, a1.y, a1.z, a1.w};
            float bb[8] = {b0.x, b0.y, b0.z, b0.w, b1.x, b1.y, b1.z, b1.w};
#pragma unroll
            for (int i = 0; i < 8; i++)
#pragma unroll
                for (int j = 0; j < 8; j++) acc[i][j] += a[i] * bb[j];
        }
        if (kt + 1 < NK) {
            int nb = cur ^ 1;
#pragma unroll
            for (int i = 0; i < 2; i++) {
                int idx = tid + i * 256;
                int row = idx >> 2, q = idx & 3;
                As[nb][q * 4 + 0][row] = ra[i].x;
                As[nb][q * 4 + 1][row] = ra[i].y;
                As[nb][q * 4 + 2][row] = ra[i].z;
                As[nb][q * 4 + 3][row] = ra[i].w;
                int kk = idx >> 5, qc = idx & 31;
                *(float4*)&Bs[nb][kk][qc * 4] = rb[i];
            }
        }
        __syncthreads();
    }

    float* ob = g_out2 + ((size_t)b * N_ + n0) * C_;
    const float* dvb = g_dv + b * N_ + n0;
#pragma unroll
    for (int i = 0; i < 8; i++) {
        int r = ty * 8 + i;
        float s = dvb[r];
        float* op = ob + (size_t)r * C_ + tx * 8;
        *(float4*)op = make_float4(acc[i][0] * s, acc[i][1] * s, acc[i][2] * s, acc[i][3] * s);
        *(float4*)(op + 4) = make_float4(acc[i][4] * s, acc[i][5] * s, acc[i][6] * s, acc[i][7] * s);
    }
}

// ============ Linear: out[r,c] = sum_k out2[r,k] * Wt[k,c] + bias[c] ============
__global__ __launch_bounds__(256) void linear_kernel(const float* __restrict__ bias,
                                                     float* __restrict__ out) {
    __shared__ float As[2][KC][SROW];
    __shared__ float Bs[2][KC][SROW];
    const int r0 = blockIdx.x * 128;  // flattened B*N rows
    const int tid = threadIdx.x;
    const int tx = tid & 15, ty = tid >> 4;

    const float* Ab = g_out2 + (size_t)r0 * C_;

    float acc[8][8];
#pragma unroll
    for (int i = 0; i < 8; i++)
#pragma unroll
        for (int j = 0; j < 8; j++) acc[i][j] = 0.f;

    float4 ra[2], rb[2];
#pragma unroll
    for (int i = 0; i < 2; i++) {
        int idx = tid + i * 256;
        int row = idx >> 2, q = idx & 3;
        ra[i] = *(const float4*)(Ab + (size_t)row * C_ + q * 4);
        int kk = idx >> 5, qc = idx & 31;
        rb[i] = *(const float4*)(g_Wt + (size_t)kk * C_ + qc * 4);
    }
#pragma unroll
    for (int i = 0; i < 2; i++) {
        int idx = tid + i * 256;
        int row = idx >> 2, q = idx & 3;
        As[0][q * 4 + 0][row] = ra[i].x;
        As[0][q * 4 + 1][row] = ra[i].y;
        As[0][q * 4 + 2][row] = ra[i].z;
        As[0][q * 4 + 3][row] = ra[i].w;
        int kk = idx >> 5, qc = idx & 31;
        *(float4*)&Bs[0][kk][qc * 4] = rb[i];
    }
    __syncthreads();

    const int NK = C_ / KC;  // 8
    for (int kt = 0; kt < NK; kt++) {
        int cur = kt & 1;
        if (kt + 1 < NK) {
            int k0 = (kt + 1) * KC;
#pragma unroll
            for (int i = 0; i < 2; i++) {
                int idx = tid + i * 256;
                int row = idx >> 2, q = idx & 3;
                ra[i] = *(const float4*)(Ab + (size_t)row * C_ + k0 + q * 4);
                int kk = idx >> 5, qc = idx & 31;
                rb[i] = *(const float4*)(g_Wt + (size_t)(k0 + kk) * C_ + qc * 4);
            }
        }
#pragma unroll
        for (int kk = 0; kk < KC; kk++) {
            float4 a0 = *(const float4*)&As[cur][kk][ty * 8];
            float4 a1 = *(const float4*)&As[cur][kk][ty * 8 + 4];
            float4 b0 = *(const float4*)&Bs[cur][kk][tx * 8];
            float4 b1 = *(const float4*)&Bs[cur][kk][tx * 8 + 4];
            float a[8] = {a0.x, a0.y, a0.z, a0.w, a1.x, a1.y, a1.z, a1.w};
            float bb[8] = {b0.x, b0.y, b0.z, b0.w, b1.x, b1.y, b1.z, b1.w};
#pragma unroll
            for (int i = 0; i < 8; i++)
#pragma unroll
                for (int j = 0; j < 8; j++) acc[i][j] += a[i] * bb[j];
        }
        if (kt + 1 < NK) {
            int nb = cur ^ 1;
#pragma unroll
            for (int i = 0; i < 2; i++) {
                int idx = tid + i * 256;
                int row = idx >> 2, q = idx & 3;
                As[nb][q * 4 + 0][row] = ra[i].x;
                As[nb][q * 4 + 1][row] = ra[i].y;
                As[nb][q * 4 + 2][row] = ra[i].z;
                As[nb][q * 4 + 3][row] = ra[i].w;
                int kk = idx >> 5, qc = idx & 31;
                *(float4*)&Bs[nb][kk][qc * 4] = rb[i];
            }
        }
        __syncthreads();
    }

    float b0v = bias[tx * 8 + 0], b1v = bias[tx * 8 + 1], b2v = bias[tx * 8 + 2], b3v = bias[tx * 8 + 3];
    float b4v = bias[tx * 8 + 4], b5v = bias[tx * 8 + 5], b6v = bias[tx * 8 + 6], b7v = bias[tx * 8 + 7];
#pragma unroll
    for (int i = 0; i < 8; i++) {
        int r = r0 + ty * 8 + i;
        float* op = out + (size_t)r * C_ + tx * 8;
        *(float4*)op = make_float4(acc[i][0] + b0v, acc[i][1] + b1v, acc[i][2] + b2v, acc[i][3] + b3v);
        *(float4*)(op + 4) = make_float4(acc[i][4] + b4v, acc[i][5] + b5v, acc[i][6] + b6v, acc[i][7] + b7v);
    }
}

// ---------------- launch ----------------
extern "C" void kernel_launch(void* const* d_in, const int* in_sizes, int n_in,
                              void* d_out, int out_size) {
    const float* x    = (const float*)d_in[0];
    const float* H    = (const float*)d_in[1];
    const float* W    = (const float*)d_in[2];
    const float* bias = (const float*)d_in[3];
    float* out = (float*)d_out;

    dv_kernel<<<B_ * N_, 128>>>(H);
    de_part_kernel<<<dim3(E_ / 256, 8, B_), 256>>>(H);
    de_final_kernel<<<(B_ * E_) / 256, 256>>>();
    wt_kernel<<<(C_ * C_) / 256, 256>>>(W);
    gemm1_kernel<<<dim3(E_ / 128, B_), 256>>>(H, x);
    gemm2_kernel<<<dim3(N_ / 128, B_), 256>>>(H);
    linear_kernel<<<(B_ * N_) / 128, 256>>>(bias, out);
}

// round 4
// speedup vs baseline: 1.0260x; 1.0260x over previous
#include <cuda_runtime.h>

#define B_   8
#define N_   4096
#define E_   2048
#define C_   128
#define EPS_ 1e-6f

#define KC   16
#define SPAD 4
#define SROW (C_ + SPAD)

// ---------------- static device scratch (no allocs allowed) ----------------
__device__ float g_dv[B_ * N_];              // Dv^{-1/2}
__device__ float g_de_part[B_ * 8 * E_];     // partial hyperedge-degree sums
__device__ float g_de_inv[B_ * E_];          // De^{-1}
__device__ float g_M[(size_t)B_ * E_ * C_];  // intermediate H^T (x Dv^-1/2) De^-1
__device__ float g_out2[(size_t)B_ * N_ * C_];
__device__ float g_Wt[C_ * C_];              // W^T (k-major)

// ---------------- Dv^{-1/2}: one block per (b,n) row ----------------
__global__ void dv_kernel(const float* __restrict__ H) {
    int row = blockIdx.x;  // b*N + n
    const float4* p = (const float4*)(H + (size_t)row * E_);
    float s = 0.f;
#pragma unroll
    for (int i = 0; i < 4; i++) {
        float4 v = p[threadIdx.x + i * 128];
        s += v.x + v.y + v.z + v.w;
    }
    __shared__ float red[4];
#pragma unroll
    for (int o = 16; o > 0; o >>= 1) s += __shfl_down_sync(0xffffffffu, s, o);
    if ((threadIdx.x & 31) == 0) red[threadIdx.x >> 5] = s;
    __syncthreads();
    if (threadIdx.x == 0) {
        float t = red[0] + red[1] + red[2] + red[3];
        g_dv[row] = rsqrtf(t + EPS_);
    }
}

// ---------------- De partial sums: column sums over 512-row chunks ----------------
__global__ void de_part_kernel(const float* __restrict__ H) {
    int e = blockIdx.x * 256 + threadIdx.x;  // gridDim.x = E/256
    int chunk = blockIdx.y;                  // 8 chunks of 512 rows
    int b = blockIdx.z;
    const float* p = H + ((size_t)b * N_ + (size_t)chunk * 512) * E_ + e;
    float s0 = 0.f, s1 = 0.f, s2 = 0.f, s3 = 0.f;
#pragma unroll 4
    for (int n = 0; n < 512; n += 4) {
        s0 += p[(size_t)(n + 0) * E_];
        s1 += p[(size_t)(n + 1) * E_];
        s2 += p[(size_t)(n + 2) * E_];
        s3 += p[(size_t)(n + 3) * E_];
    }
    g_de_part[((b * 8) + chunk) * E_ + e] = (s0 + s1) + (s2 + s3);
}

__global__ void de_final_kernel() {
    int idx = blockIdx.x * 256 + threadIdx.x;  // b*E + e
    int b = idx >> 11, e = idx & (E_ - 1);
    float s = 0.f;
#pragma unroll
    for (int c = 0; c < 8; c++) s += g_de_part[(b * 8 + c) * E_ + e];
    g_de_inv[idx] = 1.0f / (s + EPS_);
}

// ---------------- W transpose (once, tiny) ----------------
__global__ void wt_kernel(const float* __restrict__ W) {
    int i = blockIdx.x * 256 + threadIdx.x;  // c*128 + k
    int c = i >> 7, k = i & 127;
    g_Wt[k * C_ + c] = W[i];
}

// ============ GEMM1: M[b,e,c] = sum_n H[b,n,e] * x[b,n,c]*dv[b,n]; *De^-1 ============
__global__ __launch_bounds__(256) void gemm1_kernel(const float* __restrict__ H,
                                                    const float* __restrict__ x) {
    __shared__ float As[2][KC][SROW];
    __shared__ float Bs[2][KC][SROW];
    const int b = blockIdx.y;
    const int e0 = blockIdx.x * 128;
    const int tid = threadIdx.x;
    const int tx = tid & 15, ty = tid >> 4;

    const float* Hb = H + (size_t)b * N_ * E_;
    const float* xb = x + (size_t)b * N_ * C_;
    const float* dvb = g_dv + b * N_;

    float acc[8][8];
#pragma unroll
    for (int i = 0; i < 8; i++)
#pragma unroll
        for (int j = 0; j < 8; j++) acc[i][j] = 0.f;

    float4 ra[2], rb[2];
    // prologue: tile 0
#pragma unroll
    for (int i = 0; i < 2; i++) {
        int idx = tid + i * 256, kk = idx >> 5, q = idx & 31;
        ra[i] = *(const float4*)(Hb + (size_t)kk * E_ + e0 + q * 4);
        float4 v = *(const float4*)(xb + (size_t)kk * C_ + q * 4);
        float s = dvb[kk];
        v.x *= s; v.y *= s; v.z *= s; v.w *= s;
        rb[i] = v;
    }
#pragma unroll
    for (int i = 0; i < 2; i++) {
        int idx = tid + i * 256, kk = idx >> 5, q = idx & 31;
        *(float4*)&As[0][kk][q * 4] = ra[i];
        *(float4*)&Bs[0][kk][q * 4] = rb[i];
    }
    __syncthreads();

    const int NK = N_ / KC;  // 256
    for (int kt = 0; kt < NK; kt++) {
        int cur = kt & 1;
        if (kt + 1 < NK) {
            int n0 = (kt + 1) * KC;
#pragma unroll
            for (int i = 0; i < 2; i++) {
                int idx = tid + i * 256, kk = idx >> 5, q = idx & 31;
                ra[i] = *(const float4*)(Hb + (size_t)(n0 + kk) * E_ + e0 + q * 4);
                float4 v = *(const float4*)(xb + (size_t)(n0 + kk) * C_ + q * 4);
                float s = dvb[n0 + kk];
                v.x *= s; v.y *= s; v.z *= s; v.w *= s;
                rb[i] = v;
            }
        }
#pragma unroll
        for (int kk = 0; kk < KC; kk++) {
            float4 a0 = *(const float4*)&As[cur][kk][ty * 8];
            float4 a1 = *(const float4*)&As[cur][kk][ty * 8 + 4];
            float4 b0 = *(const float4*)&Bs[cur][kk][tx * 8];
            float4 b1 = *(const float4*)&Bs[cur][kk][tx * 8 + 4];
            float a[8] = {a0.x, a0.y, a0.z, a0.w, a1.x, a1.y, a1.z, a1.w};
            float bb[8] = {b0.x, b0.y, b0.z, b0.w, b1.x, b1.y, b1.z, b1.w};
#pragma unroll
            for (int i = 0; i < 8; i++)
#pragma unroll
                for (int j = 0; j < 8; j++) acc[i][j] += a[i] * bb[j];
        }
        if (kt + 1 < NK) {
            int nb = cur ^ 1;
#pragma unroll
            for (int i = 0; i < 2; i++) {
                int idx = tid + i * 256, kk = idx >> 5, q = idx & 31;
                *(float4*)&As[nb][kk][q * 4] = ra[i];
                *(float4*)&Bs[nb][kk][q * 4] = rb[i];
            }
        }
        __syncthreads();
    }

    float* Mb = g_M + (size_t)b * E_ * C_;
    const float* deb = g_de_inv + b * E_;
#pragma unroll
    for (int i = 0; i < 8; i++) {
        int e = e0 + ty * 8 + i;
        float s = deb[e];
        float* op = Mb + (size_t)e * C_ + tx * 8;
        *(float4*)op = make_float4(acc[i][0] * s, acc[i][1] * s, acc[i][2] * s, acc[i][3] * s);
        *(float4*)(op + 4) = make_float4(acc[i][4] * s, acc[i][5] * s, acc[i][6] * s, acc[i][7] * s);
    }
}

// ============ GEMM2: out2[b,n,c] = (sum_e H[b,n,e] * M[b,e,c]) * dv[b,n] ============
__global__ __launch_bounds__(256) void gemm2_kernel(const float* __restrict__ H) {
    __shared__ float As[2][KC][SROW];
    __shared__ float Bs[2][KC][SROW];
    const int b = blockIdx.y;
    const int n0 = blockIdx.x * 128;
    const int tid = threadIdx.x;
    const int tx = tid & 15, ty = tid >> 4;

    const float* Hb = H + ((size_t)b * N_ + n0) * E_;
    const float* Mb = g_M + (size_t)b * E_ * C_;

    float acc[8][8];
#pragma unroll
    for (int i = 0; i < 8; i++)
#pragma unroll
        for (int j = 0; j < 8; j++) acc[i][j] = 0.f;

    float4 ra[2], rb[2];
#pragma unroll
    for (int i = 0; i < 2; i++) {
        int idx = tid + i * 256;
        int row = idx >> 2, q = idx & 3;
        ra[i] = *(const float4*)(Hb + (size_t)row * E_ + q * 4);
        int kk = idx >> 5, qc = idx & 31;
        rb[i] = *(const float4*)(Mb + (size_t)kk * C_ + qc * 4);
    }
#pragma unroll
    for (int i = 0; i < 2; i++) {
        int idx = tid + i * 256;
        int row = idx >> 2, q = idx & 3;
        As[0][q * 4 + 0][row] = ra[i].x;
        As[0][q * 4 + 1][row] = ra[i].y;
        As[0][q * 4 + 2][row] = ra[i].z;
        As[0][q * 4 + 3][row] = ra[i].w;
        int kk = idx >> 5, qc = idx & 31;
        *(float4*)&Bs[0][kk][qc * 4] = rb[i];
    }
    __syncthreads();

    const int NK = E_ / KC;  // 128
    for (int kt = 0; kt < NK; kt++) {
        int cur = kt & 1;
        if (kt + 1 < NK) {
            int k0 = (kt + 1) * KC;
#pragma unroll
            for (int i = 0; i < 2; i++) {
                int idx = tid + i * 256;
                int row = idx >> 2, q = idx & 3;
                ra[i] = *(const float4*)(Hb + (size_t)row * E_ + k0 + q * 4);
                int kk = idx >> 5, qc = idx & 31;
                rb[i] = *(const float4*)(Mb + (size_t)(k0 + kk) * C_ + qc * 4);
            }
        }
#pragma unroll
        for (int kk = 0; kk < KC; kk++) {
            float4 a0 = *(const float4*)&As[cur][kk][ty * 8];
            float4 a1 = *(const float4*)&As[cur][kk][ty * 8 + 4];
            float4 b0 = *(const float4*)&Bs[cur][kk][tx * 8];
            float4 b1 = *(const float4*)&Bs[cur][kk][tx * 8 + 4];
            float a[8] = {a0.x, a0.y, a0.z, a0.w, a1.x, a1.y, a1.z, a1.w};
            float bb[8] = {b0.x, b0.y, b0.z, b0.w, b1.x, b1.y, b1.z, b1.w};
#pragma unroll
            for (int i = 0; i < 8; i++)
#pragma unroll
                for (int j = 0; j < 8; j++) acc[i][j] += a[i] * bb[j];
        }
        if (kt + 1 < NK) {
            int nb = cur ^ 1;
#pragma unroll
            for (int i = 0; i < 2; i++) {
                int idx = tid + i * 256;
                int row = idx >> 2, q = idx & 3;
                As[nb][q * 4 + 0][row] = ra[i].x;
                As[nb][q * 4 + 1][row] = ra[i].y;
                As[nb][q * 4 + 2][row] = ra[i].z;
                As[nb][q * 4 + 3][row] = ra[i].w;
                int kk = idx >> 5, qc = idx & 31;
                *(float4*)&Bs[nb][kk][qc * 4] = rb[i];
            }
        }
        __syncthreads();
    }

    float* ob = g_out2 + ((size_t)b * N_ + n0) * C_;
    const float* dvb = g_dv + b * N_ + n0;
#pragma unroll
    for (int i = 0; i < 8; i++) {
        int r = ty * 8 + i;
        float s = dvb[r];
        float* op = ob + (size_t)r * C_ + tx * 8;
        *(float4*)op = make_float4(acc[i][0] * s, acc[i][1] * s, acc[i][2] * s, acc[i][3] * s);
        *(float4*)(op + 4) = make_float4(acc[i][4] * s, acc[i][5] * s, acc[i][6] * s, acc[i][7] * s);
    }
}

// ============ Linear: out[r,c] = sum_k out2[r,k] * Wt[k,c] + bias[c] ============
__global__ __launch_bounds__(256) void linear_kernel(const float* __restrict__ bias,
                                                     float* __restrict__ out) {
    __shared__ float As[2][KC][SROW];
    __shared__ float Bs[2][KC][SROW];
    const int r0 = blockIdx.x * 128;  // flattened B*N rows
    const int tid = threadIdx.x;
    const int tx = tid & 15, ty = tid >> 4;

    const float* Ab = g_out2 + (size_t)r0 * C_;

    float acc[8][8];
#pragma unroll
    for (int i = 0; i < 8; i++)
#pragma unroll
        for (int j = 0; j < 8; j++) acc[i][j] = 0.f;

    float4 ra[2], rb[2];
#pragma unroll
    for (int i = 0; i < 2; i++) {
        int idx = tid + i * 256;
        int row = idx >> 2, q = idx & 3;
        ra[i] = *(const float4*)(Ab + (size_t)row * C_ + q * 4);
        int kk = idx >> 5, qc = idx & 31;
        rb[i] = *(const float4*)(g_Wt + (size_t)kk * C_ + qc * 4);
    }
#pragma unroll
    for (int i = 0; i < 2; i++) {
        int idx = tid + i * 256;
        int row = idx >> 2, q = idx & 3;
        As[0][q * 4 + 0][row] = ra[i].x;
        As[0][q * 4 + 1][row] = ra[i].y;
        As[0][q * 4 + 2][row] = ra[i].z;
        As[0][q * 4 + 3][row] = ra[i].w;
        int kk = idx >> 5, qc = idx & 31;
        *(float4*)&Bs[0][kk][qc * 4] = rb[i];
    }
    __syncthreads();

    const int NK = C_ / KC;  // 8
    for (int kt = 0; kt < NK; kt++) {
        int cur = kt & 1;
        if (kt + 1 < NK) {
            int k0 = (kt + 1) * KC;
#pragma unroll
            for (int i = 0; i < 2; i++) {
                int idx = tid + i * 256;
                int row = idx >> 2, q = idx & 3;
                ra[i] = *(const float4*)(Ab + (size_t)row * C_ + k0 + q * 4);
                int kk = idx >> 5, qc = idx & 31;
                rb[i] = *(const float4*)(g_Wt + (size_t)(k0 + kk) * C_ + qc * 4);
            }
        }
#pragma unroll
        for (int kk = 0; kk < KC; kk++) {
            float4 a0 = *(const float4*)&As[cur][kk][ty * 8];
            float4 a1 = *(const float4*)&As[cur][kk][ty * 8 + 4];
            float4 b0 = *(const float4*)&Bs[cur][kk][tx * 8];
            float4 b1 = *(const float4*)&Bs[cur][kk][tx * 8 + 4];
            float a[8] = {a0.x, a0.y, a0.z, a0.w, a1.x, a1.y, a1.z, a1.w};
            float bb[8] = {b0.x, b0.y, b0.z, b0.w, b1.x, b1.y, b1.z, b1.w};
#pragma unroll
            for (int i = 0; i < 8; i++)
#pragma unroll
                for (int j = 0; j < 8; j++) acc[i][j] += a[i] * bb[j];
        }
        if (kt + 1 < NK) {
            int nb = cur ^ 1;
#pragma unroll
            for (int i = 0; i < 2; i++) {
                int idx = tid + i * 256;
                int row = idx >> 2, q = idx & 3;
                As[nb][q * 4 + 0][row] = ra[i].x;
                As[nb][q * 4 + 1][row] = ra[i].y;
                As[nb][q * 4 + 2][row] = ra[i].z;
                As[nb][q * 4 + 3][row] = ra[i].w;
                int kk = idx >> 5, qc = idx & 31;
                *(float4*)&Bs[nb][kk][qc * 4] = rb[i];
            }
        }
        __syncthreads();
    }

    float b0v = bias[tx * 8 + 0], b1v = bias[tx * 8 + 1], b2v = bias[tx * 8 + 2], b3v = bias[tx * 8 + 3];
    float b4v = bias[tx * 8 + 4], b5v = bias[tx * 8 + 5], b6v = bias[tx * 8 + 6], b7v = bias[tx * 8 + 7];
#pragma unroll
    for (int i = 0; i < 8; i++) {
        int r = r0 + ty * 8 + i;
        float* op = out + (size_t)r * C_ + tx * 8;
        *(float4*)op = make_float4(acc[i][0] + b0v, acc[i][1] + b1v, acc[i][2] + b2v, acc[i][3] + b3v);
        *(float4*)(op + 4) = make_float4(acc[i][4] + b4v, acc[i][5] + b5v, acc[i][6] + b6v, acc[i][7] + b7v);
    }
}

// ---------------- launch ----------------
extern "C" void kernel_launch(void* const* d_in, const int* in_sizes, int n_in,
                              void* d_out, int out_size) {
    const float* x    = (const float*)d_in[0];
    const float* H    = (const float*)d_in[1];
    const float* W    = (const float*)d_in[2];
    const float* bias = (const float*)d_in[3];
    float* out = (float*)d_out;

    dv_kernel<<<B_ * N_, 128>>>(H);
    de_part_kernel<<<dim3(E_ / 256, 8, B_), 256>>>(H);
    de_final_kernel<<<(B_ * E_) / 256, 256>>>();
    wt_kernel<<<(C_ * C_) / 256, 256>>>(W);
    gemm1_kernel<<<dim3(E_ / 128, B_), 256>>>(H, x);
    gemm2_kernel<<<dim3(N_ / 128, B_), 256>>>(H);
    linear_kernel<<<(B_ * N_) / 128, 256>>>(bias, out);
}

// round 7
// speedup vs baseline: 2.2030x; 2.1472x over previous
#include <cuda_runtime.h>
#include <cuda_bf16.h>
#include <cstdint>

#define B_   8
#define N_   4096
#define E_   2048
#define C_   128
#define EPS_ 1e-6f

#define KT   64
#define STAGE_BYTES 65536
#define A_HI 0
#define A_LO 16384
#define B_HI 32768
#define B_LO 49152
#define TILE0 1024
#define DSMEM (1024 + 1024 + 2 * STAGE_BYTES)

#define SW(o) ((o) ^ ((((uint32_t)(o)) >> 3) & 0x70u))

// ---------------- static device scratch ----------------
__device__ float g_dv[B_ * N_];
__device__ float g_de_part[B_ * 8 * E_];
__device__ float g_de_inv[B_ * E_];
__device__ __nv_bfloat16 g_xt_hi[(size_t)B_ * C_ * N_];
__device__ __nv_bfloat16 g_xt_lo[(size_t)B_ * C_ * N_];
__device__ __nv_bfloat16 g_W_hi[C_ * C_];
__device__ __nv_bfloat16 g_W_lo[C_ * C_];
__device__ __nv_bfloat16 g_Mt_hi[(size_t)B_ * C_ * E_];
__device__ __nv_bfloat16 g_Mt_lo[(size_t)B_ * C_ * E_];
__device__ __nv_bfloat16 g_o2_hi[(size_t)B_ * N_ * C_];
__device__ __nv_bfloat16 g_o2_lo[(size_t)B_ * N_ * C_];

// ---------------- helpers ----------------
__device__ __forceinline__ uint32_t s2u(const void* p) {
    uint32_t a;
    asm("{ .reg .u64 t; cvta.to.shared.u64 t, %1; cvt.u32.u64 %0, t; }" : "=r"(a) : "l"(p));
    return a;
}
__device__ __forceinline__ void sts32(uint32_t a, uint32_t x) {
    asm volatile("st.shared.b32 [%0], %1;" :: "r"(a), "r"(x) : "memory");
}
__device__ __forceinline__ void sts64(uint32_t a, uint32_t x, uint32_t y) {
    asm volatile("st.shared.v2.b32 [%0], {%1, %2};" :: "r"(a), "r"(x), "r"(y) : "memory");
}
__device__ __forceinline__ void sts128(uint32_t a, uint4 v) {
    asm volatile("st.shared.v4.b32 [%0], {%1, %2, %3, %4};" :: "r"(a), "r"(v.x), "r"(v.y), "r"(v.z), "r"(v.w) : "memory");
}
__device__ __forceinline__ void ldsm4(uint32_t r[4], uint32_t addr) {
    asm volatile("ldmatrix.sync.aligned.m8n8.x4.shared.b16 {%0,%1,%2,%3}, [%4];"
        : "=r"(r[0]), "=r"(r[1]), "=r"(r[2]), "=r"(r[3]) : "r"(addr));
}
__device__ __forceinline__ void mma16816(float c[4], const uint32_t a[4], uint32_t b0, uint32_t b1) {
    asm volatile("mma.sync.aligned.m16n8k16.row.col.f32.bf16.bf16.f32 "
        "{%0,%1,%2,%3}, {%4,%5,%6,%7}, {%8,%9}, {%0,%1,%2,%3};"
        : "+f"(c[0]), "+f"(c[1]), "+f"(c[2]), "+f"(c[3])
        : "r"(a[0]), "r"(a[1]), "r"(a[2]), "r"(a[3]), "r"(b0), "r"(b1));
}
__device__ __forceinline__ void split2(float f0, float f1, uint32_t& h, uint32_t& l) {
    unsigned short h0 = __bfloat16_as_ushort(__float2bfloat16(f0));
    unsigned short h1 = __bfloat16_as_ushort(__float2bfloat16(f1));
    float r0 = f0 - __bfloat162float(__ushort_as_bfloat16(h0));
    float r1 = f1 - __bfloat162float(__ushort_as_bfloat16(h1));
    unsigned short l0 = __bfloat16_as_ushort(__float2bfloat16(r0));
    unsigned short l1 = __bfloat16_as_ushort(__float2bfloat16(r1));
    h = (uint32_t)h0 | ((uint32_t)h1 << 16);
    l = (uint32_t)l0 | ((uint32_t)l1 << 16);
}

// ---------------- degree + staging kernels (proven in R1) ----------------
__global__ void dv_kernel(const float* __restrict__ H) {
    int row = blockIdx.x;
    const float4* p = (const float4*)(H + (size_t)row * E_);
    float s = 0.f;
#pragma unroll
    for (int i = 0; i < 4; i++) {
        float4 v = p[threadIdx.x + i * 128];
        s += v.x + v.y + v.z + v.w;
    }
    __shared__ float red[4];
#pragma unroll
    for (int o = 16; o > 0; o >>= 1) s += __shfl_down_sync(0xffffffffu, s, o);
    if ((threadIdx.x & 31) == 0) red[threadIdx.x >> 5] = s;
    __syncthreads();
    if (threadIdx.x == 0) g_dv[row] = rsqrtf(red[0] + red[1] + red[2] + red[3] + EPS_);
}

__global__ void de_part_kernel(const float* __restrict__ H) {
    int e = blockIdx.x * 256 + threadIdx.x;
    int chunk = blockIdx.y, b = blockIdx.z;
    const float* p = H + ((size_t)b * N_ + (size_t)chunk * 512) * E_ + e;
    float s0 = 0.f, s1 = 0.f, s2 = 0.f, s3 = 0.f;
#pragma unroll 4
    for (int n = 0; n < 512; n += 4) {
        s0 += p[(size_t)(n + 0) * E_];
        s1 += p[(size_t)(n + 1) * E_];
        s2 += p[(size_t)(n + 2) * E_];
        s3 += p[(size_t)(n + 3) * E_];
    }
    g_de_part[((b * 8) + chunk) * E_ + e] = (s0 + s1) + (s2 + s3);
}

__global__ void de_final_kernel() {
    int idx = blockIdx.x * 256 + threadIdx.x;
    int b = idx >> 11, e = idx & (E_ - 1);
    float s = 0.f;
#pragma unroll
    for (int c = 0; c < 8; c++) s += g_de_part[(b * 8 + c) * E_ + e];
    g_de_inv[idx] = 1.0f / (s + EPS_);
}

// xt[b][c][n] = split( x[b][n][c] * dv[b][n] )
__global__ void xt_kernel(const float* __restrict__ x) {
    __shared__ float t[32][33];
    int b = blockIdx.z, n0 = blockIdx.x * 32, c0 = blockIdx.y * 32;
    int tx = threadIdx.x, ty = threadIdx.y;
#pragma unroll
    for (int i = 0; i < 4; i++) {
        int n = n0 + ty + i * 8;
        t[ty + i * 8][tx] = x[((size_t)(b * N_ + n)) * C_ + c0 + tx] * g_dv[b * N_ + n];
    }
    __syncthreads();
#pragma unroll
    for (int i = 0; i < 4; i++) {
        int c = c0 + ty + i * 8;
        float f = t[tx][ty + i * 8];
        __nv_bfloat16 h = __float2bfloat16(f);
        __nv_bfloat16 l = __float2bfloat16(f - __bfloat162float(h));
        size_t o = ((size_t)(b * C_ + c)) * N_ + n0 + tx;
        g_xt_hi[o] = h;
        g_xt_lo[o] = l;
    }
}

__global__ void wsplit_kernel(const float* __restrict__ W) {
    int i = blockIdx.x * 256 + threadIdx.x;
    float f = W[i];
    __nv_bfloat16 h = __float2bfloat16(f);
    g_W_hi[i] = h;
    g_W_lo[i] = __float2bfloat16(f - __bfloat162float(h));
}

// ---------------- templated HMMA GEMM ----------------
// MODE 0: Mt[c, e]  = (xt . H^T_tile) * De^-1[e]   rows=c(128), cols=e blk, K=n  grid(16,8)
// MODE 1: o2[n, c]  = (H . Mt)        * dv[n]      rows=n blk, cols=c(128), K=e  grid(32,8)
// MODE 2: out[r, c] = (o2 . W) + bias[c]           rows=r blk, cols=c(128), K=128 grid(256)
template<int MODE>
__global__ __launch_bounds__(256) void gemm_tc(const float* __restrict__ H,
                                               const float* __restrict__ bias,
                                               float* __restrict__ outp) {
    constexpr int NK = (MODE == 0) ? N_ / KT : ((MODE == 1) ? E_ / KT : C_ / KT);
    extern __shared__ char smem[];
    uint32_t raw = s2u(smem);
    uint32_t sb = (raw + 1023u) & ~1023u;
    float* scS = (float*)(smem + (sb - raw));
    const int tid = threadIdx.x;
    const int lane = tid & 31, wid = tid >> 5;
    const int warp_m = wid >> 2, warp_n = wid & 3;
    const int m0 = blockIdx.x * 128;
    const int b = (MODE == 2) ? 0 : blockIdx.y;

    if (tid < 128) {
        if (MODE == 0) scS[tid] = g_de_inv[b * E_ + m0 + tid];
        if (MODE == 1) scS[tid] = g_dv[b * N_ + m0 + tid];
        if (MODE == 2) scS[tid] = bias[tid];
    }

    // prefetch registers
    uint4 pA[8], pB[8];
    float4 pF[8];
    float pb0[16], pb1[16];
    const int p_ = (tid >> 5) * 4 + ((tid & 31) >> 3);  // MODE0 B transpose lane map
    const int elo = tid & 7;

    const __nv_bfloat16* xh = g_xt_hi + (size_t)b * C_ * N_;
    const __nv_bfloat16* xl = g_xt_lo + (size_t)b * C_ * N_;
    const __nv_bfloat16* mh = g_Mt_hi + (size_t)b * C_ * E_;
    const __nv_bfloat16* ml = g_Mt_lo + (size_t)b * C_ * E_;
    const float* hb = H + ((MODE == 0) ? ((size_t)b * N_ * E_ + m0)
                                       : ((size_t)(b * N_ + m0) * E_));

    auto loadT = [&](int kt) {
        int koff = kt * KT;
        if constexpr (MODE == 0) {
#pragma unroll
            for (int i = 0; i < 4; i++) {
                int idx = tid + i * 256, row = idx >> 3, q = idx & 7;
                pA[i]     = *(const uint4*)(xh + (size_t)row * N_ + koff + q * 8);
                pA[4 + i] = *(const uint4*)(xl + (size_t)row * N_ + koff + q * 8);
            }
#pragma unroll
            for (int i = 0; i < 16; i++) {
                int e = i * 8 + elo;
                pb0[i] = hb[(size_t)(koff + 2 * p_) * E_ + e];
                pb1[i] = hb[(size_t)(koff + 2 * p_ + 1) * E_ + e];
            }
        } else if constexpr (MODE == 1) {
#pragma unroll
            for (int i = 0; i < 8; i++) {
                int idx = tid + i * 256, row = idx >> 4, q = idx & 15;
                pF[i] = *(const float4*)(hb + (size_t)row * E_ + koff + q * 4);
            }
#pragma unroll
            for (int i = 0; i < 4; i++) {
                int idx = tid + i * 256, row = idx >> 3, q = idx & 7;
                pB[i]     = *(const uint4*)(mh + (size_t)row * E_ + koff + q * 8);
                pB[4 + i] = *(const uint4*)(ml + (size_t)row * E_ + koff + q * 8);
            }
        } else {
#pragma unroll
            for (int i = 0; i < 4; i++) {
                int idx = tid + i * 256, row = idx >> 3, q = idx & 7;
                pA[i]     = *(const uint4*)(g_o2_hi + (size_t)(m0 + row) * C_ + koff + q * 8);
                pA[4 + i] = *(const uint4*)(g_o2_lo + (size_t)(m0 + row) * C_ + koff + q * 8);
                pB[i]     = *(const uint4*)(g_W_hi + (size_t)row * C_ + koff + q * 8);
                pB[4 + i] = *(const uint4*)(g_W_lo + (size_t)row * C_ + koff + q * 8);
            }
        }
    };
    auto storeT = [&](int s) {
        uint32_t base = sb + TILE0 + s * STAGE_BYTES;
        if constexpr (MODE == 0) {
#pragma unroll
            for (int i = 0; i < 4; i++) {
                int idx = tid + i * 256, row = idx >> 3, q = idx & 7;
                uint32_t off = SW(row * 128 + q * 16);
                sts128(base + A_HI + off, pA[i]);
                sts128(base + A_LO + off, pA[4 + i]);
            }
#pragma unroll
            for (int i = 0; i < 16; i++) {
                int e = i * 8 + elo;
                uint32_t h, l;
                split2(pb0[i], pb1[i], h, l);
                uint32_t off = SW(e * 128 + p_ * 4);
                sts32(base + B_HI + off, h);
                sts32(base + B_LO + off, l);
            }
        } else if constexpr (MODE == 1) {
#pragma unroll
            for (int i = 0; i < 8; i++) {
                int idx = tid + i * 256, row = idx >> 4, q = idx & 15;
                uint32_t h0, l0, h1, l1;
                split2(pF[i].x, pF[i].y, h0, l0);
                split2(pF[i].z, pF[i].w, h1, l1);
                uint32_t off = SW(row * 128 + q * 8);
                sts64(base + A_HI + off, h0, h1);
                sts64(base + A_LO + off, l0, l1);
            }
#pragma unroll
            for (int i = 0; i < 4; i++) {
                int idx = tid + i * 256, row = idx >> 3, q = idx & 7;
                uint32_t off = SW(row * 128 + q * 16);
                sts128(base + B_HI + off, pB[i]);
                sts128(base + B_LO + off, pB[4 + i]);
            }
        } else {
#pragma unroll
            for (int i = 0; i < 4; i++) {
                int idx = tid + i * 256, row = idx >> 3, q = idx & 7;
                uint32_t off = SW(row * 128 + q * 16);
                sts128(base + A_HI + off, pA[i]);
                sts128(base + A_LO + off, pA[4 + i]);
                sts128(base + B_HI + off, pB[i]);
                sts128(base + B_LO + off, pB[4 + i]);
            }
        }
    };

    float acc[4][4][4];
#pragma unroll
    for (int i = 0; i < 4; i++)
#pragma unroll
        for (int j = 0; j < 4; j++)
#pragma unroll
            for (int k = 0; k < 4; k++) acc[i][j][k] = 0.f;

    // ldmatrix address components
    const int a_row = warp_m * 64 + (lane & 15);
    const int a_kb  = (lane >> 4) * 16;
    const int b_row = warp_n * 32 + (lane & 7) + ((lane >> 4) << 3);
    const int b_kb  = ((lane >> 3) & 1) * 16;

    loadT(0);
    storeT(0);
    __syncthreads();

    for (int kt = 0; kt < NK; kt++) {
        int cur = kt & 1;
        if (kt + 1 < NK) loadT(kt + 1);   // LDGs in flight during MMAs

        uint32_t base = sb + TILE0 + cur * STAGE_BYTES;
#pragma unroll
        for (int ks = 0; ks < 4; ks++) {
            uint32_t ah[4][4], al[4][4], bh[2][4], bl[2][4];
#pragma unroll
            for (int i = 0; i < 4; i++) {
                uint32_t off = SW((a_row + i * 16) * 128 + ks * 32 + a_kb);
                ldsm4(ah[i], base + A_HI + off);
                ldsm4(al[i], base + A_LO + off);
            }
#pragma unroll
            for (int j2 = 0; j2 < 2; j2++) {
                uint32_t off = SW((b_row + j2 * 16) * 128 + ks * 32 + b_kb);
                ldsm4(bh[j2], base + B_HI + off);
                ldsm4(bl[j2], base + B_LO + off);
            }
#pragma unroll
            for (int i = 0; i < 4; i++)
#pragma unroll
                for (int j = 0; j < 4; j++) {
                    int j2 = j >> 1, sub = (j & 1) * 2;
                    mma16816(acc[i][j], ah[i], bh[j2][sub], bh[j2][sub + 1]);
                    mma16816(acc[i][j], ah[i], bl[j2][sub], bl[j2][sub + 1]);
                    mma16816(acc[i][j], al[i], bh[j2][sub], bh[j2][sub + 1]);
                }
        }
        if (kt + 1 < NK) storeT(cur ^ 1);
        __syncthreads();
    }

    // ---------------- epilogue ----------------
    const int r4 = lane >> 2, tig = lane & 3;
#pragma unroll
    for (int i = 0; i < 4; i++) {
#pragma unroll
        for (int j = 0; j < 4; j++) {
            int row0 = warp_m * 64 + i * 16 + r4;
            int row1 = row0 + 8;
            int cl = warp_n * 32 + j * 8 + tig * 2;
            float v00 = acc[i][j][0], v01 = acc[i][j][1];
            float v10 = acc[i][j][2], v11 = acc[i][j][3];
            if constexpr (MODE == 0) {
                float s0 = scS[cl], s1 = scS[cl + 1];
                uint32_t h, l;
                size_t o0 = ((size_t)(b * C_ + row0)) * E_ + m0 + cl;
                size_t o1 = ((size_t)(b * C_ + row1)) * E_ + m0 + cl;
                split2(v00 * s0, v01 * s1, h, l);
                *(uint32_t*)(g_Mt_hi + o0) = h; *(uint32_t*)(g_Mt_lo + o0) = l;
                split2(v10 * s0, v11 * s1, h, l);
                *(uint32_t*)(g_Mt_hi + o1) = h; *(uint32_t*)(g_Mt_lo + o1) = l;
            } else if constexpr (MODE == 1) {
                float s0 = scS[row0], s1 = scS[row1];
                uint32_t h, l;
                size_t o0 = ((size_t)(b * N_ + m0 + row0)) * C_ + cl;
                size_t o1 = ((size_t)(b * N_ + m0 + row1)) * C_ + cl;
                split2(v00 * s0, v01 * s0, h, l);
                *(uint32_t*)(g_o2_hi + o0) = h; *(uint32_t*)(g_o2_lo + o0) = l;
                split2(v10 * s1, v11 * s1, h, l);
                *(uint32_t*)(g_o2_hi + o1) = h; *(uint32_t*)(g_o2_lo + o1) = l;
            } else {
                float s0 = scS[cl], s1 = scS[cl + 1];
                float* op0 = outp + (size_t)(m0 + row0) * C_ + cl;
                float* op1 = outp + (size_t)(m0 + row1) * C_ + cl;
                op0[0] = v00 + s0; op0[1] = v01 + s1;
                op1[0] = v10 + s0; op1[1] = v11 + s1;
            }
        }
    }
}

// ---------------- launch ----------------
extern "C" void kernel_launch(void* const* d_in, const int* in_sizes, int n_in,
                              void* d_out, int out_size) {
    const float* x    = (const float*)d_in[0];
    const float* H    = (const float*)d_in[1];
    const float* W    = (const float*)d_in[2];
    const float* bias = (const float*)d_in[3];
    float* out = (float*)d_out;

    cudaFuncSetAttribute(gemm_tc<0>, cudaFuncAttributeMaxDynamicSharedMemorySize, DSMEM);
    cudaFuncSetAttribute(gemm_tc<1>, cudaFuncAttributeMaxDynamicSharedMemorySize, DSMEM);
    cudaFuncSetAttribute(gemm_tc<2>, cudaFuncAttributeMaxDynamicSharedMemorySize, DSMEM);

    dv_kernel<<<B_ * N_, 128>>>(H);
    de_part_kernel<<<dim3(E_ / 256, 8, B_), 256>>>(H);
    de_final_kernel<<<(B_ * E_) / 256, 256>>>();
    xt_kernel<<<dim3(N_ / 32, C_ / 32, B_), dim3(32, 8)>>>(x);
    wsplit_kernel<<<(C_ * C_) / 256, 256>>>(W);
    gemm_tc<0><<<dim3(E_ / 128, B_), 256, DSMEM>>>(H, nullptr, nullptr);
    gemm_tc<1><<<dim3(N_ / 128, B_), 256, DSMEM>>>(H, nullptr, nullptr);
    gemm_tc<2><<<(B_ * N_) / 128, 256, DSMEM>>>(nullptr, bias, out);
}